// round 8
// baseline (speedup 1.0000x reference)
#include <cuda_runtime.h>
#include <math.h>

#define BB 64
#define TT 512
#define II 256
#define OO 1024
#define MM 8
#define IMM 2048
#define NBLK 148
#define NT 512
#define KSR 12                 // REC k-splits per tile
#define KSA 8                  // ACT k-splits per tile
#define NRECT 8                // REC tiles of 256 cols
#define NACTT 4                // ACT tiles of 256 cols
#define NREC (NRECT * KSR)     // 96
#define NACT (NACTT * KSA)     // 32
#define NGEMM (NREC + NACT)    // 128
#define NGATE 16
#define GATE0 NGEMM            // 128..143
#define RELEASER 147
// smem: sB[2][16][256] + sA_dup[2][16][192]  (floats)
#define SB_FLOATS (2 * 16 * 256)
#define SA_FLOATS (2 * 16 * 192)
#define DYN_SMEM ((SB_FLOATS + SA_FLOATS) * 4)   // 57344 B

// ---------------- persistent device state ------------------------------------
__device__ float g_H[2][BB * OO];          // h carry (double buffered)
__device__ float g_XP[2][BB * IMM];        // x_pred carry (double buffered)
__device__ float g_Pact[KSA][BB * OO];     // split-K partials (acts)
__device__ float g_Prec[KSR][BB * IMM];    // split-K partials (acts_rec)
__device__ float g_lse[IMM];
__device__ float g_gate[BB * MM];
__device__ volatile unsigned g_parr[NRECT + NACTT][16];  // per-tile arrival flags
__device__ volatile unsigned g_gdone[NGATE];             // gate finished flags
__device__ volatile unsigned g_garr[NGATE];              // gate mini-barrier
__device__ volatile unsigned g_ggen;
__device__ volatile unsigned g_arr[NBLK];                // grid arrival flags
__device__ volatile unsigned g_gen;                      // grid release gen

// ---------------- grid barrier helpers (monotonic, replay-safe) --------------
__device__ __forceinline__ void grid_arrive(unsigned tgt) {
    __syncthreads();
    if (threadIdx.x == 0) { __threadfence(); g_arr[blockIdx.x] = tgt; }
}
__device__ __forceinline__ void grid_wait(unsigned tgt) {
    const int tid = threadIdx.x;
    if (blockIdx.x == RELEASER) {
        if (tid < NBLK) { while ((int)(g_arr[tid] - tgt) < 0) {} }
        __syncthreads();
        if (tid == 0) { __threadfence(); g_gen = tgt; }
    } else {
        if (tid == 0) {
            while ((int)(g_gen - tgt) < 0) { __nanosleep(32); }
            __threadfence();
        }
    }
    __syncthreads();
}

// ---------------- packed f32x2 helpers ---------------------------------------
__device__ __forceinline__ void ffma2(unsigned long long& d, unsigned long long a,
                                      unsigned long long b) {
    asm("fma.rn.f32x2 %0, %1, %2, %0;" : "+l"(d) : "l"(a), "l"(b));
}
__device__ __forceinline__ float2 unpack2(unsigned long long v) {
    float2 r;
    asm("mov.b64 {%0, %1}, %2;" : "=f"(r.x), "=f"(r.y) : "l"(v));
    return r;
}

// ---------------- 64x256-tile GEMM chunk, conflict-free dup-A layout ---------
// P[b][col0+c] = sum_{k in [k0, k0+16*nsub)} A[b][k] * W(col,k)
// A[b][k] = xb[b*xs + k]      (k <  II)
//         = cb[b*cs + (k-II)] (k >= II, cross-SM carry -> ldcg)
// W(c,k)  = W1[c*ld1 + k] (k<II) else W2[c*ld2 + (k-II)]
__device__ __forceinline__ void gemm_unit(
    const float* xb, int xs, const float* cb, int cs,
    const float* __restrict__ W1, int ld1,
    const float* __restrict__ W2, int ld2,
    int col0, int k0, int nsub,
    float* __restrict__ P, int NC, float* dynsh)
{
    float* sB = dynsh;                 // [2][16][256]        k-major W
    float* sA = dynsh + SB_FLOATS;     // [2][16][192]        duplicated A
    const int tid = threadIdx.x;
    const int wid = tid >> 5, lane = tid & 31;
    const int bgrp = wid & 1;          // 2 groups of 32 batches
    const int cgrp = wid >> 1;         // 8 groups of 32 cols
    const int qb = lane >> 2;          // 8 x 4-batch quads
    const int qc = lane & 3;           // 4 x 8-col groups
    const int aoff = bgrp * 96 + qb * 12;   // float offset within sA k-row
    const int woff = cgrp * 32 + qc * 8;    // float offset within sB k-row
    // staging roles
    const int jc = tid & 255;               // W col this thread stages
    const int kh = (tid >> 8) * 8;          // W k-offset (0 or 8)
    const int sb_b = tid & 63;              // A stager batch (tid < 256)
    const int sb_kq = (tid >> 6) & 3;       // A stager k-quad
    const int sa_off = (sb_b >> 5) * 96 + ((sb_b & 31) >> 2) * 12 + (sb_b & 3) * 2;

    unsigned long long acc[4][4];
#pragma unroll
    for (int b = 0; b < 4; b++)
#pragma unroll
        for (int c = 0; c < 4; c++) acc[b][c] = 0ull;

    const int j = col0 + jc;
    float wbuf[8]; float4 abuf;
    {   // prefetch chunk 0
        const int kb = k0;
        const float* ws = ((kb < II) ? (W1 + (size_t)j * ld1 + kb)
                                     : (W2 + (size_t)j * ld2 + (kb - II))) + kh;
        *(float4*)&wbuf[0] = __ldg((const float4*)ws);
        *(float4*)&wbuf[4] = __ldg((const float4*)(ws + 4));
        if (tid < 256) {
            const float* as = (kb < II) ? (xb + sb_b * xs + kb + sb_kq * 4)
                                        : (cb + sb_b * cs + (kb - II) + sb_kq * 4);
            abuf = __ldcg((const float4*)as);
        }
    }
    {   // stage chunk 0 into buffer 0
        float* sBd = sB;
        float* sAd = sA;
#pragma unroll
        for (int i = 0; i < 8; i++) sBd[(kh + i) * 256 + jc] = wbuf[i];
        if (tid < 256) {
            float* d = sAd + (sb_kq * 4) * 192 + sa_off;
            *(float2*)(d)       = make_float2(abuf.x, abuf.x);
            *(float2*)(d + 192) = make_float2(abuf.y, abuf.y);
            *(float2*)(d + 384) = make_float2(abuf.z, abuf.z);
            *(float2*)(d + 576) = make_float2(abuf.w, abuf.w);
        }
    }
    __syncthreads();

    for (int s = 0; s < nsub; s++) {
        const float* sBb = sB + (s & 1) * (16 * 256);
        const float* sAb = sA + (s & 1) * (16 * 192);

        if (s + 1 < nsub) {   // prefetch next chunk (latency hidden by compute)
            const int kb = k0 + (s + 1) * 16;
            const float* ws = ((kb < II) ? (W1 + (size_t)j * ld1 + kb)
                                         : (W2 + (size_t)j * ld2 + (kb - II))) + kh;
            *(float4*)&wbuf[0] = __ldg((const float4*)ws);
            *(float4*)&wbuf[4] = __ldg((const float4*)(ws + 4));
            if (tid < 256) {
                const float* as = (kb < II) ? (xb + sb_b * xs + kb + sb_kq * 4)
                                            : (cb + sb_b * cs + (kb - II) + sb_kq * 4);
                abuf = __ldcg((const float4*)as);
            }
        }

        // 16-k compute: 4 conflict-free LDS.128 + 16 FFMA2 per k, no MOVs
#pragma unroll
        for (int k = 0; k < 16; k++) {
            const float* pa = sAb + k * 192 + aoff;
            ulonglong2 a01 = *(const ulonglong2*)pa;        // (a0,a0),(a1,a1)
            ulonglong2 a23 = *(const ulonglong2*)(pa + 4);  // (a2,a2),(a3,a3)
            const float* pw = sBb + k * 256 + woff;
            ulonglong2 w01 = *(const ulonglong2*)pw;        // col pairs (0,1),(2,3)
            ulonglong2 w23 = *(const ulonglong2*)(pw + 4);  // col pairs (4,5),(6,7)
            ffma2(acc[0][0], a01.x, w01.x); ffma2(acc[0][1], a01.x, w01.y);
            ffma2(acc[0][2], a01.x, w23.x); ffma2(acc[0][3], a01.x, w23.y);
            ffma2(acc[1][0], a01.y, w01.x); ffma2(acc[1][1], a01.y, w01.y);
            ffma2(acc[1][2], a01.y, w23.x); ffma2(acc[1][3], a01.y, w23.y);
            ffma2(acc[2][0], a23.x, w01.x); ffma2(acc[2][1], a23.x, w01.y);
            ffma2(acc[2][2], a23.x, w23.x); ffma2(acc[2][3], a23.x, w23.y);
            ffma2(acc[3][0], a23.y, w01.x); ffma2(acc[3][1], a23.y, w01.y);
            ffma2(acc[3][2], a23.y, w23.x); ffma2(acc[3][3], a23.y, w23.y);
        }

        if (s + 1 < nsub) {   // stage next chunk into the other buffer
            float* sBd = sB + ((s + 1) & 1) * (16 * 256);
            float* sAd = sA + ((s + 1) & 1) * (16 * 192);
#pragma unroll
            for (int i = 0; i < 8; i++) sBd[(kh + i) * 256 + jc] = wbuf[i];
            if (tid < 256) {
                float* d = sAd + (sb_kq * 4) * 192 + sa_off;
                *(float2*)(d)       = make_float2(abuf.x, abuf.x);
                *(float2*)(d + 192) = make_float2(abuf.y, abuf.y);
                *(float2*)(d + 384) = make_float2(abuf.z, abuf.z);
                *(float2*)(d + 576) = make_float2(abuf.w, abuf.w);
            }
        }
        __syncthreads();
    }

    // write partial tile: lane owns 4 batches x 8 cols
#pragma unroll
    for (int b = 0; b < 4; b++) {
        float2 v0 = unpack2(acc[b][0]), v1 = unpack2(acc[b][1]);
        float2 v2 = unpack2(acc[b][2]), v3 = unpack2(acc[b][3]);
        const int bb = bgrp * 32 + qb * 4 + b;
        float* dst = P + (size_t)bb * NC + col0 + cgrp * 32 + qc * 8;
        *(float4*)dst       = make_float4(v0.x, v0.y, v1.x, v1.y);
        *(float4*)(dst + 4) = make_float4(v2.x, v2.y, v3.x, v3.y);
    }
}

// ---------------- gate work (16 CTAs), overlapped with GEMM phase -------------
__device__ __forceinline__ void gate_work(
    int t, const float* __restrict__ XPold, const float* __restrict__ x,
    const float* __restrict__ periods, const float* __restrict__ shifts,
    float* __restrict__ out_ps, unsigned tgt)
{
    const int gi = blockIdx.x - GATE0;       // 0..15
    const int tid = threadIdx.x, wid = tid >> 5, lane = tid & 31;

    // pass 1: batch-axis logsumexp for 128 cols
#pragma unroll
    for (int it = 0; it < 8; it++) {
        const int col = gi * 128 + it * 16 + wid;
        float v0 = __ldcg(&XPold[lane * IMM + col]);
        float v1 = __ldcg(&XPold[(lane + 32) * IMM + col]);
        float m = fmaxf(v0, v1);
#pragma unroll
        for (int off = 16; off > 0; off >>= 1)
            m = fmaxf(m, __shfl_xor_sync(0xffffffffu, m, off));
        float s = expf(v0 - m) + expf(v1 - m);
#pragma unroll
        for (int off = 16; off > 0; off >>= 1)
            s += __shfl_xor_sync(0xffffffffu, s, off);
        if (lane == 0) g_lse[col] = m + logf(s);
    }
    // mini-barrier among the 16 gate CTAs
    __syncthreads();
    if (tid == 0) { __threadfence(); g_garr[gi] = tgt; }
    if (gi == 0) {
        if (tid < NGATE) { while ((int)(g_garr[tid] - tgt) < 0) {} }
        __syncthreads();
        if (tid == 0) { __threadfence(); g_ggen = tgt; }
        __syncthreads();
    } else {
        if (tid == 0) { while ((int)(g_ggen - tgt) < 0) {} __threadfence(); }
        __syncthreads();
    }
    // pass 2: surprisal -> mp -> gate, 2 (b,m) pairs per warp
#pragma unroll
    for (int uu = 0; uu < 2; uu++) {
        const int u = gi * 32 + wid * 2 + uu;
        const int b = u >> 3, mo = u & 7;
        float s = 0.f;
#pragma unroll
        for (int i0 = 0; i0 < II; i0 += 32) {
            const int i = i0 + lane;
            s += (__ldcg(&XPold[b * IMM + mo * II + i]) - __ldcg(&g_lse[mo * II + i]))
                 * __ldg(&x[((size_t)b * TT + t) * II + i]);
        }
#pragma unroll
        for (int off = 16; off > 0; off >>= 1)
            s += __shfl_xor_sync(0xffffffffu, s, off);
        if (lane == 0) {
            const float mp = s * (1.f / (float)II) * __ldg(&periods[mo]);
            out_ps[((size_t)b * TT + t) * MM + mo] = mp;
            g_gate[u] = (sinf((float)t * mp + __ldg(&shifts[mo])) + 1.f) * 0.5f;
        }
    }
    __syncthreads();
    if (tid == 0) { __threadfence(); g_gdone[gi] = tgt; }
}

// ---------------- persistent kernel ------------------------------------------
__global__ void __launch_bounds__(NT, 1)
cwrnn_kernel(const float* __restrict__ x, const float* __restrict__ W_in,
             const float* __restrict__ b_in, const float* __restrict__ W_h,
             const float* __restrict__ W_ir, const float* __restrict__ b_ir,
             const float* __restrict__ W_hr, const float* __restrict__ periods,
             const float* __restrict__ shifts, float* __restrict__ out)
{
    extern __shared__ float dynsh[];
    const int bid = blockIdx.x, tid = threadIdx.x;
    const int gstep = NBLK * NT;
    float* out_ys = out;
    float* out_hf = out + (size_t)BB * TT * OO;
    float* out_ps = out_hf + BB * OO;

    const unsigned base = g_gen;   // monotonic across graph replays

    for (int idx = bid * NT + tid; idx < BB * OO; idx += gstep) g_H[0][idx] = 0.f;
    for (int idx = bid * NT + tid; idx < BB * IMM; idx += gstep) g_XP[0][idx] = 0.f;
    grid_arrive(base + 1);
    grid_wait(base + 1);

    for (int t = 0; t < TT; t++) {
        const unsigned tgt = base + 2 + t;
        const int p = t & 1;
        const float* xb = x + (size_t)t * II;

        if (bid < NREC) {
            // ===== REC GEMM + fused in-tile reduction ========================
            const int tile = bid / KSR, ks = bid - tile * KSR;
            gemm_unit(xb, TT * II, g_XP[p], IMM, W_ir, II, W_hr, IMM,
                      tile * 256, ks * 192, 12, g_Prec[ks], IMM, dynsh);
            __syncthreads();
            if (tid == 0) { __threadfence(); g_parr[tile][ks] = tgt; }
            if (tid < KSR) { while ((int)(g_parr[tile][tid] - tgt) < 0) {} }
            __syncthreads();
            const int w  = (ks < 8) ? 22 : 20;
            const int s0 = (ks < 8) ? 22 * ks : 176 + 20 * (ks - 8);
            const int cbase = tile * 256 + s0;
            for (int i = tid; i < BB * w; i += NT) {
                const int b = i / w, jj = cbase + (i - b * w);
                float s = __ldg(&b_ir[jj]);
#pragma unroll
                for (int k2 = 0; k2 < KSR; k2++)
                    s += __ldcg(&g_Prec[k2][b * IMM + jj]);
                g_XP[p ^ 1][b * IMM + jj] = tanhf(s);
            }
            grid_arrive(tgt);
        } else if (bid < NGEMM) {
            // ===== ACT GEMM + fused reduction + gate blend + outputs =========
            const int v = bid - NREC, tile = v / KSA, ks = v - tile * KSA;
            gemm_unit(xb, TT * II, g_H[p], OO, W_in, II, W_h, OO,
                      tile * 256, ks * 160, 10, g_Pact[ks], OO, dynsh);
            __syncthreads();
            if (tid == 0) { __threadfence(); g_parr[NRECT + tile][ks] = tgt; }
            if (tid < KSA) { while ((int)(g_parr[NRECT + tile][tid] - tgt) < 0) {} }
            if (tid < NGATE) {
                while ((int)(g_gdone[tid] - tgt) < 0) { __nanosleep(32); }
            }
            __syncthreads();
            const int cbase = tile * 256 + ks * 32;
#pragma unroll
            for (int it = 0; it < 4; it++) {
                const int i = it * NT + tid;
                const int b = i >> 5, o = cbase + (i & 31);
                float s = __ldg(&b_in[o]);
#pragma unroll
                for (int k2 = 0; k2 < KSA; k2++)
                    s += __ldcg(&g_Pact[k2][b * OO + o]);
                const float a = tanhf(s);
                const float g = __ldcg(&g_gate[b * MM + (o >> 7)]);
                const float h = __ldcg(&g_H[p][b * OO + o]);
                const float y = (1.f - g) * a + g * h;
                out_ys[((size_t)b * TT + t) * OO + o] = y;
                g_H[p ^ 1][b * OO + o] = y;
                if (t == TT - 1) out_hf[b * OO + o] = y;
            }
            grid_arrive(tgt);
        } else if (bid < GATE0 + NGATE) {
            gate_work(t, g_XP[p], x, periods, shifts, out_ps, tgt);
            grid_arrive(tgt);
        } else {
            grid_arrive(tgt);   // spares (incl. releaser)
        }
        grid_wait(tgt);
    }
}

extern "C" void kernel_launch(void* const* d_in, const int* in_sizes, int n_in,
                              void* d_out, int out_size) {
    (void)in_sizes; (void)n_in; (void)out_size;
    const float* x       = (const float*)d_in[0];
    const float* W_in    = (const float*)d_in[1];
    const float* b_in    = (const float*)d_in[2];
    const float* W_h     = (const float*)d_in[3];
    const float* W_ir    = (const float*)d_in[4];
    const float* b_ir    = (const float*)d_in[5];
    const float* W_hr    = (const float*)d_in[6];
    const float* periods = (const float*)d_in[7];
    const float* shifts  = (const float*)d_in[8];
    float* out = (float*)d_out;

    cudaFuncSetAttribute(cwrnn_kernel,
                         cudaFuncAttributeMaxDynamicSharedMemorySize, DYN_SMEM);
    cwrnn_kernel<<<NBLK, NT, DYN_SMEM>>>(x, W_in, b_in, W_h, W_ir, b_ir, W_hr,
                                         periods, shifts, out);
}